// round 11
// baseline (speedup 1.0000x reference)
#include <cuda_runtime.h>

#define NWL 112
#define NW  111
#define ATM 84
#define THREADS 256
#define WPB 8
#define BLOCKS 296            // 148 SMs * 2 resident (smem-limited)
#define TROWS 128             // rows per smem tile
#define SROW 111              // smem row stride in floats: gcd(111,32)=1 -> conflict-free
#define CH4 4096              // float4 per dynamic base-loss chunk (64KB)

#define DYN_SMEM_BYTES ((2 * TROWS * SROW + NW) * 4)

__device__ double g_base_sum;   // all zero-init at load; reset by finalizer each run
__device__ double g_wfa_sum;
__device__ unsigned long long g_cnt;
__device__ unsigned int g_done;
__device__ unsigned int g_tile;
__device__ unsigned int g_chunk;

extern __shared__ float dsm[];

__global__ void __launch_bounds__(THREADS, 2)
wfa_kernel(const float* __restrict__ stokes,
           const float* __restrict__ pred,
           const float* __restrict__ targ,
           const float* __restrict__ wl,
           float* __restrict__ out, int B)
{
    float* sI = dsm;
    float* sV = dsm + TROWS * SROW;
    float* sg = dsm + 2 * TROWS * SROW;   // inverse wavelength gradient [111]

    const int tid  = threadIdx.x;
    const int lane = tid & 31;
    const int warp = tid >> 5;
    const unsigned FULL = 0xffffffffu;
    const float inv_cal = 1.0f / (4.6686e-13f * (6301.5f * 6301.5f) * 1.5f);

    // one-time: ig[j] = 1 / gradient(wl)[j]
    if (tid < NW) {
        float g;
        if (tid == 0)           g = wl[1] - wl[0];
        else if (tid == NW - 1) g = wl[NW - 1] - wl[NW - 2];
        else                    g = 0.5f * (wl[tid + 1] - wl[tid - 1]);
        sg[tid] = 1.0f / g;
    }

    double local_wfa = 0.0;
    float  local_base = 0.f;
    unsigned int local_cnt = 0;

    const int n_tiles = (B + TROWS - 1) / TROWS;
    const int r    = tid >> 1;        // row within tile (0..127)
    const int half = tid & 1;         // wavelength half

    __shared__ int s_tile;
    // ================= phase 1: WFA tiles (dynamic) =================
    for (;;) {
        __syncthreads();              // protects smem reuse & s_tile
        if (tid == 0) s_tile = (int)atomicAdd(&g_tile, 1u);
        __syncthreads();
        const int tile = s_tile;
        if (tile >= n_tiles) break;
        const int base_row = tile * TROWS;

        // ---- load: scalar coalesced LDG -> conflict-free STS ----
        const int total_s = 2 * TROWS * NW;   // 28416
        for (int k = tid; k < total_s; k += THREADS) {
            const int seg = (k >= TROWS * NW) ? 1 : 0;
            const int rem = k - seg * (TROWS * NW);
            const int row = rem / NW;
            const int j   = rem - row * NW;
            const int grow = base_row + row;
            float v = 0.f;
            if (grow < B)
                v = __ldg(stokes + (size_t)grow * (4 * NWL) + seg * (3 * NWL) + j);
            (seg ? sV : sI)[row * SROW + j] = v;
        }
        __syncthreads();

        // ---- compute: 2 threads per row, serial smem reduction ----
        const int grow = base_row + r;
        const float* I = sI + r * SROW;
        const float* V = sV + r * SROW;
        float sd = 0.f, sv = 0.f, sdd = 0.f, sdv = 0.f;

        const int j0 = half ? 56 : 1;
        const int j1 = half ? 110 : 56;
        float Im1 = I[j0 - 1], I0 = I[j0];
        #pragma unroll 4
        for (int j = j0; j < j1; ++j) {
            float Ip1 = I[j + 1];
            float di  = 0.5f * (Ip1 - Im1) * sg[j];
            float vv  = V[j];
            sd  += di;  sv  += vv;
            sdd += di * di;  sdv += di * vv;
            Im1 = I0; I0 = Ip1;
        }
        if (!half) {                   // endpoint j = 0
            float di = (I[1] - I[0]) * sg[0];
            float vv = V[0];
            sd += di; sv += vv; sdd += di * di; sdv += di * vv;
        } else {                       // endpoint j = 110
            float di = (I[110] - I[109]) * sg[110];
            float vv = V[110];
            sd += di; sv += vv; sdd += di * di; sdv += di * vv;
        }

        // early epilogue loads (cover latency under the shuffles)
        float pa3 = 0.f, pa7 = 0.f, pa11 = 0.f;
        if (!half && grow < B) {
            const float* a = pred + (size_t)grow * ATM;
            pa3  = __ldg(a + 3);
            pa7  = __ldg(a + 7);
            pa11 = __ldg(a + 11);
        }

        // combine halves: ONE butterfly step per accumulator
        sd  += __shfl_xor_sync(FULL, sd,  1);
        sv  += __shfl_xor_sync(FULL, sv,  1);
        sdd += __shfl_xor_sync(FULL, sdd, 1);
        sdv += __shfl_xor_sync(FULL, sdv, 1);

        if (!half && grow < B) {       // 128 parallel epilogues per tile
            const float n = (float)NW;
            float p0   = (n * sdv - sd * sv) / (n * sdd - sd * sd);
            float blos = -p0 * inv_cal;
            if (fabsf(blos) < 100.0f) {
                float pb = (pa3 + pa7 + pa11) * (1.0f / 3.0f);
                local_wfa += (double)fabsf(log10f(fabsf(pb)   + 1e-10f) -
                                           log10f(fabsf(blos) + 1e-10f));
                local_cnt += 1u;
            }
        }
    }

    // ================= phase 2: base loss (dynamic 64KB chunks) =================
    const size_t total4  = ((size_t)B * ATM) >> 2;
    const int n_chunks = (int)((total4 + CH4 - 1) / CH4);
    const float4* p4 = (const float4*)pred;
    const float4* t4 = (const float4*)targ;
    __shared__ int s_chunk;
    for (;;) {
        __syncthreads();
        if (tid == 0) s_chunk = (int)atomicAdd(&g_chunk, 1u);
        __syncthreads();
        const int ch = s_chunk;
        if (ch >= n_chunks) break;
        size_t i   = (size_t)ch * CH4 + tid;
        size_t end = (size_t)(ch + 1) * CH4;
        if (end > total4) end = total4;
        float a0 = 0.f, a1 = 0.f;
        #pragma unroll 4
        for (; i < end; i += THREADS) {
            float4 p = p4[i], t = t4[i];
            a0 += fabsf(p.x - t.x) + fabsf(p.y - t.y);
            a1 += fabsf(p.z - t.z) + fabsf(p.w - t.w);
        }
        local_base += a0 + a1;
    }

    // ================= reduction + finalize =================
    #pragma unroll
    for (int off = 16; off; off >>= 1) {
        local_base += __shfl_xor_sync(FULL, local_base, off);
        local_wfa  += __shfl_xor_sync(FULL, local_wfa,  off);
        local_cnt  += __shfl_xor_sync(FULL, local_cnt,  off);
    }
    __shared__ double s_wfa[WPB];
    __shared__ float  s_base[WPB];
    __shared__ unsigned int s_cnt[WPB];
    if (lane == 0) { s_wfa[warp] = local_wfa; s_base[warp] = local_base; s_cnt[warp] = local_cnt; }
    __syncthreads();

    __shared__ bool s_last;
    if (tid == 0) {
        double w = 0.0, bs = 0.0; unsigned long long c = 0;
        #pragma unroll
        for (int i = 0; i < WPB; i++) { w += s_wfa[i]; bs += (double)s_base[i]; c += s_cnt[i]; }
        atomicAdd(&g_base_sum, bs);
        if (w != 0.0) atomicAdd(&g_wfa_sum, w);
        if (c)        atomicAdd(&g_cnt, c);
        __threadfence();
        unsigned int prev = atomicAdd(&g_done, 1u);
        s_last = (prev == gridDim.x - 1);
    }
    __syncthreads();

    if (s_last && tid == 0) {
        double base = *((volatile double*)&g_base_sum) / ((double)B * (double)ATM);
        unsigned long long cnt = *((volatile unsigned long long*)&g_cnt);
        double wfa_m = *((volatile double*)&g_wfa_sum) / (double)(cnt > 0 ? cnt : 1);
        bool apply = (base < 0.0004) && (cnt > 0);
        out[0] = apply ? (float)(0.5 * base + 0.5 * wfa_m) : (float)base;
        out[1] = (float)base;
        out[2] = apply ? (float)wfa_m : 0.0f;
        // reset ALL mutable state for next graph replay
        g_base_sum = 0.0;
        g_wfa_sum  = 0.0;
        g_cnt      = 0ull;
        g_done     = 0u;
        g_tile     = 0u;
        g_chunk    = 0u;
        __threadfence();
    }
}

extern "C" void kernel_launch(void* const* d_in, const int* in_sizes, int n_in,
                              void* d_out, int out_size) {
    const float* stokes = (const float*)d_in[0];   // (B, 4, 112)
    const float* pred   = (const float*)d_in[1];   // (B, 84)
    const float* targ   = (const float*)d_in[2];   // (B, 84)
    const float* wl     = (const float*)d_in[3];   // (112,)
    const int B = in_sizes[0] / (4 * NWL);

    cudaFuncSetAttribute(wfa_kernel, cudaFuncAttributeMaxDynamicSharedMemorySize,
                         DYN_SMEM_BYTES);
    wfa_kernel<<<BLOCKS, THREADS, DYN_SMEM_BYTES>>>(stokes, pred, targ, wl,
                                                    (float*)d_out, B);
}

// round 14
// speedup vs baseline: 2.1857x; 2.1857x over previous
#include <cuda_runtime.h>

#define NWL 112
#define NW  111
#define ATM 84
#define THREADS 256
#define WPB (THREADS / 32)
#define WFA_WARPS 5
#define BASE_WARPS (WPB - WFA_WARPS)
#define BLOCKS 740            // 148 SMs * 5 resident blocks -> single wave

__device__ double g_base_sum;   // zero-init at load; reset by finalizer each run
__device__ double g_wfa_sum;
__device__ unsigned long long g_cnt;
__device__ unsigned int g_done;

__global__ void __launch_bounds__(THREADS, 5)
wfa_fused_kernel(const float* __restrict__ stokes,
                 const float* __restrict__ pred,
                 const float* __restrict__ targ,
                 const float* __restrict__ wl,
                 float* __restrict__ out, int B) {
    const int tid   = threadIdx.x;
    const int lane  = tid & 31;
    const int warp  = tid >> 5;
    const unsigned FULL = 0xffffffffu;

    double local_wfa = 0.0;
    float  local_base = 0.f;
    unsigned int local_cnt = 0;

    if (warp < WFA_WARPS) {
        // ================= WFA warps: warp per row-pair, pipelined =================
        const int gwarp  = blockIdx.x * WFA_WARPS + warp;
        const int nwarps = BLOCKS * WFA_WARPS;
        const float inv_cal = 1.0f / (4.6686e-13f * (6301.5f * 6301.5f) * 1.5f);
        const bool act = (lane < 28);            // 28 float4 cover [0..111]

        // per-lane inverse wavelength gradient (row-invariant)
        float4 ig = make_float4(0.f, 0.f, 0.f, 0.f);
        float4 w4 = act ? ((const float4*)wl)[lane] : make_float4(0.f, 0.f, 0.f, 0.f);
        float wprev = __shfl_up_sync(FULL, w4.w, 1);
        float wnext = __shfl_down_sync(FULL, w4.x, 1);
        if (act) {
            float g0 = (lane == 0)  ? (w4.y - w4.x) : 0.5f * (w4.y - wprev);
            float g1 = 0.5f * (w4.z - w4.x);
            float g2 = (lane == 27) ? (w4.z - w4.y) : 0.5f * (w4.w - w4.y);
            ig.x = 1.0f / g0;
            ig.y = 1.0f / g1;
            ig.z = 1.0f / g2;
            ig.w = (lane == 27) ? 0.0f : 1.0f / (0.5f * (wnext - w4.z));  // j=111 excluded
        }

        const int pstep = 2 * nwarps;
        int b = 2 * gwarp;
        float4 iv0, vv0, iv1, vv1;
        if (b < B && act) {
            const float* r0 = stokes + (size_t)b * (4 * NWL);
            iv0 = ((const float4*)r0)[lane];
            vv0 = ((const float4*)(r0 + 3 * NWL))[lane];
            iv1 = ((const float4*)(r0 + 4 * NWL))[lane];
            vv1 = ((const float4*)(r0 + 7 * NWL))[lane];
        } else {
            iv0 = iv1 = vv0 = vv1 = make_float4(0.f,0.f,0.f,0.f);
        }

        while (b < B) {
            const int bn = b + pstep;
            float4 ivn0, vvn0, ivn1, vvn1;
            if (bn < B && act) {                  // prefetch next pair
                const float* rn = stokes + (size_t)bn * (4 * NWL);
                ivn0 = ((const float4*)rn)[lane];
                vvn0 = ((const float4*)(rn + 3 * NWL))[lane];
                ivn1 = ((const float4*)(rn + 4 * NWL))[lane];
                vvn1 = ((const float4*)(rn + 7 * NWL))[lane];
            } else {
                ivn0 = ivn1 = vvn0 = vvn1 = make_float4(0.f,0.f,0.f,0.f);
            }

            float ip0 = __shfl_up_sync(FULL, iv0.w, 1);
            float in0 = __shfl_down_sync(FULL, iv0.x, 1);
            float ip1 = __shfl_up_sync(FULL, iv1.w, 1);
            float in1 = __shfl_down_sync(FULL, iv1.x, 1);

            float v0=0.f,v1=0.f,v2=0.f,v3=0.f,v4=0.f,v5=0.f,v6=0.f,v7=0.f;
            if (act) {
                float d0 = ((lane == 0)  ? (iv0.y - iv0.x) : 0.5f * (iv0.y - ip0)) * ig.x;
                float d1 = 0.5f * (iv0.z - iv0.x) * ig.y;
                float d2 = ((lane == 27) ? (iv0.z - iv0.y) : 0.5f * (iv0.w - iv0.y)) * ig.z;
                float d3 = 0.5f * (in0 - iv0.z) * ig.w;
                float vw0 = (lane == 27) ? 0.0f : vv0.w;
                v0 = d0 + d1 + d2 + d3;
                v1 = vv0.x + vv0.y + vv0.z + vw0;
                v2 = d0*d0 + d1*d1 + d2*d2 + d3*d3;
                v3 = d0*vv0.x + d1*vv0.y + d2*vv0.z + d3*vw0;
                float e0 = ((lane == 0)  ? (iv1.y - iv1.x) : 0.5f * (iv1.y - ip1)) * ig.x;
                float e1 = 0.5f * (iv1.z - iv1.x) * ig.y;
                float e2 = ((lane == 27) ? (iv1.z - iv1.y) : 0.5f * (iv1.w - iv1.y)) * ig.z;
                float e3 = 0.5f * (in1 - iv1.z) * ig.w;
                float vw1 = (lane == 27) ? 0.0f : vv1.w;
                v4 = e0 + e1 + e2 + e3;
                v5 = vv1.x + vv1.y + vv1.z + vw1;
                v6 = e0*e0 + e1*e1 + e2*e2 + e3*e3;
                v7 = e0*vv1.x + e1*vv1.y + e2*vv1.z + e3*vw1;
            }

            // joint 8-value packed butterfly: 16 SHFL
            v0 += __shfl_xor_sync(FULL, v0, 1);
            v1 += __shfl_xor_sync(FULL, v1, 1);
            v2 += __shfl_xor_sync(FULL, v2, 1);
            v3 += __shfl_xor_sync(FULL, v3, 1);
            v4 += __shfl_xor_sync(FULL, v4, 1);
            v5 += __shfl_xor_sync(FULL, v5, 1);
            v6 += __shfl_xor_sync(FULL, v6, 1);
            v7 += __shfl_xor_sync(FULL, v7, 1);
            float p0 = (lane & 1) ? v1 : v0;
            float p1 = (lane & 1) ? v3 : v2;
            float p2 = (lane & 1) ? v5 : v4;
            float p3 = (lane & 1) ? v7 : v6;
            p0 += __shfl_xor_sync(FULL, p0, 2);
            p1 += __shfl_xor_sync(FULL, p1, 2);
            p2 += __shfl_xor_sync(FULL, p2, 2);
            p3 += __shfl_xor_sync(FULL, p3, 2);
            float q0 = (lane & 2) ? p1 : p0;
            float q1 = (lane & 2) ? p3 : p2;
            q0 += __shfl_xor_sync(FULL, q0, 4);
            q1 += __shfl_xor_sync(FULL, q1, 4);
            float r = (lane & 4) ? q1 : q0;
            r += __shfl_xor_sync(FULL, r, 8);
            r += __shfl_xor_sync(FULL, r, 16);
            // lane l holds total of value index (l&7)

            const int base = lane & 4;
            float sd_t  = __shfl_sync(FULL, r, base + 0);
            float sv_t  = __shfl_sync(FULL, r, base + 1);
            float sdd_t = __shfl_sync(FULL, r, base + 2);
            float sdv_t = __shfl_sync(FULL, r, base + 3);

            if ((lane & 27) == 0) {       // lanes 0 and 4 run epilogues concurrently
                const int myb = b + (lane >> 2);
                const float n = (float)NW;
                float pp   = (n * sdv_t - sd_t * sv_t) / (n * sdd_t - sd_t * sd_t);
                float blos = -pp * inv_cal;
                if (fabsf(blos) < 100.0f) {
                    const float* aptr = pred + (size_t)myb * ATM;
                    float pb = (aptr[3] + aptr[7] + aptr[11]) * (1.0f / 3.0f);
                    local_wfa += (double)fabsf(log10f(fabsf(pb)  + 1e-10f) -
                                               log10f(fabsf(blos) + 1e-10f));
                    local_cnt += 1u;
                }
            }
            iv0 = ivn0; vv0 = vvn0; iv1 = ivn1; vv1 = vvn1; b = bn;
        }
    } else {
        // ================= base warps: mean |pred - targ| =================
        const int bwarp   = blockIdx.x * BASE_WARPS + (warp - WFA_WARPS);
        const size_t total4 = ((size_t)B * ATM) >> 2;
        const float4* p4 = (const float4*)pred;
        const float4* t4 = (const float4*)targ;
        const size_t stride = (size_t)BLOCKS * BASE_WARPS * 32;
        size_t i = (size_t)bwarp * 32 + lane;

        float a0 = 0.f, a1 = 0.f, a2 = 0.f, a3 = 0.f;
        // 4-deep unroll: 8 independent float4 loads in flight
        for (; i + 3 * stride < total4; i += 4 * stride) {
            float4 pA = p4[i];              float4 tA = t4[i];
            float4 pB = p4[i + stride];     float4 tB = t4[i + stride];
            float4 pC = p4[i + 2 * stride]; float4 tC = t4[i + 2 * stride];
            float4 pD = p4[i + 3 * stride]; float4 tD = t4[i + 3 * stride];
            a0 += fabsf(pA.x - tA.x) + fabsf(pA.y - tA.y) + fabsf(pA.z - tA.z) + fabsf(pA.w - tA.w);
            a1 += fabsf(pB.x - tB.x) + fabsf(pB.y - tB.y) + fabsf(pB.z - tB.z) + fabsf(pB.w - tB.w);
            a2 += fabsf(pC.x - tC.x) + fabsf(pC.y - tC.y) + fabsf(pC.z - tC.z) + fabsf(pC.w - tC.w);
            a3 += fabsf(pD.x - tD.x) + fabsf(pD.y - tD.y) + fabsf(pD.z - tD.z) + fabsf(pD.w - tD.w);
        }
        for (; i < total4; i += stride) {
            float4 p = p4[i], t = t4[i];
            a0 += fabsf(p.x - t.x) + fabsf(p.y - t.y) + fabsf(p.z - t.z) + fabsf(p.w - t.w);
        }
        local_base = (a0 + a1) + (a2 + a3);
    }

    // ------------- warp + block reduction -------------
    #pragma unroll
    for (int off = 16; off; off >>= 1) {
        local_base += __shfl_xor_sync(FULL, local_base, off);
        local_wfa  += __shfl_xor_sync(FULL, local_wfa,  off);
        local_cnt  += __shfl_xor_sync(FULL, local_cnt,  off);
    }
    __shared__ double s_wfa[WPB];
    __shared__ float  s_base[WPB];
    __shared__ unsigned int s_cnt[WPB];
    if (lane == 0) { s_wfa[warp] = local_wfa; s_base[warp] = local_base; s_cnt[warp] = local_cnt; }
    __syncthreads();

    __shared__ bool s_last;
    if (tid == 0) {
        double w = 0.0, bs = 0.0; unsigned long long c = 0;
        #pragma unroll
        for (int i = 0; i < WPB; i++) { w += s_wfa[i]; bs += (double)s_base[i]; c += s_cnt[i]; }
        atomicAdd(&g_base_sum, bs);
        if (w != 0.0) atomicAdd(&g_wfa_sum, w);
        if (c)        atomicAdd(&g_cnt, c);
        __threadfence();
        unsigned int prev = atomicAdd(&g_done, 1u);
        s_last = (prev == gridDim.x - 1);
    }
    __syncthreads();

    // ------------- last block finalizes + resets for next replay -------------
    if (s_last && tid == 0) {
        double base = *((volatile double*)&g_base_sum) / ((double)B * (double)ATM);
        unsigned long long cnt = *((volatile unsigned long long*)&g_cnt);
        double wfa_m = *((volatile double*)&g_wfa_sum) / (double)(cnt > 0 ? cnt : 1);
        bool apply = (base < 0.0004) && (cnt > 0);
        out[0] = apply ? (float)(0.5 * base + 0.5 * wfa_m) : (float)base;
        out[1] = (float)base;
        out[2] = apply ? (float)wfa_m : 0.0f;
        g_base_sum = 0.0;
        g_wfa_sum  = 0.0;
        g_cnt      = 0ull;
        g_done     = 0u;
        __threadfence();
    }
}

extern "C" void kernel_launch(void* const* d_in, const int* in_sizes, int n_in,
                              void* d_out, int out_size) {
    const float* stokes = (const float*)d_in[0];   // (B, 4, 112)
    const float* pred   = (const float*)d_in[1];   // (B, 84)
    const float* targ   = (const float*)d_in[2];   // (B, 84)
    const float* wl     = (const float*)d_in[3];   // (112,)
    const int B = in_sizes[0] / (4 * NWL);
    wfa_fused_kernel<<<BLOCKS, THREADS>>>(stokes, pred, targ, wl, (float*)d_out, B);
}

// round 16
// speedup vs baseline: 2.2012x; 1.0071x over previous
#include <cuda_runtime.h>

#define NWL 112
#define NW  111
#define ATM 84
#define THREADS 256
#define WPB (THREADS / 32)
#define WFA_WARPS 6
#define BASE_WARPS (WPB - WFA_WARPS)
#define BLOCKS 740            // 148 SMs * 5 resident blocks -> single wave
#define CHUNK4 512            // float4 per base-loss ticket (16KB pred+targ)

__device__ double g_base_sum;   // zero-init at load; reset by finalizer each run
__device__ double g_wfa_sum;
__device__ unsigned long long g_cnt;
__device__ unsigned int g_done;
__device__ unsigned int g_chunk;

__global__ void __launch_bounds__(THREADS, 5)
wfa_fused_kernel(const float* __restrict__ stokes,
                 const float* __restrict__ pred,
                 const float* __restrict__ targ,
                 const float* __restrict__ wl,
                 float* __restrict__ out, int B) {
    const int tid   = threadIdx.x;
    const int lane  = tid & 31;
    const int warp  = tid >> 5;
    const unsigned FULL = 0xffffffffu;

    double local_wfa = 0.0;
    float  local_base = 0.f;
    unsigned int local_cnt = 0;

    if (warp < WFA_WARPS) {
        // ================= WFA warps: warp per row-pair, pipelined =================
        const int gwarp  = blockIdx.x * WFA_WARPS + warp;
        const int nwarps = BLOCKS * WFA_WARPS;
        const float inv_cal = 1.0f / (4.6686e-13f * (6301.5f * 6301.5f) * 1.5f);
        const bool act = (lane < 28);            // 28 float4 cover [0..111]

        // per-lane inverse wavelength gradient (row-invariant)
        float4 ig = make_float4(0.f, 0.f, 0.f, 0.f);
        float4 w4 = act ? ((const float4*)wl)[lane] : make_float4(0.f, 0.f, 0.f, 0.f);
        float wprev = __shfl_up_sync(FULL, w4.w, 1);
        float wnext = __shfl_down_sync(FULL, w4.x, 1);
        if (act) {
            float g0 = (lane == 0)  ? (w4.y - w4.x) : 0.5f * (w4.y - wprev);
            float g1 = 0.5f * (w4.z - w4.x);
            float g2 = (lane == 27) ? (w4.z - w4.y) : 0.5f * (w4.w - w4.y);
            ig.x = 1.0f / g0;
            ig.y = 1.0f / g1;
            ig.z = 1.0f / g2;
            ig.w = (lane == 27) ? 0.0f : 1.0f / (0.5f * (wnext - w4.z));  // j=111 excluded
        }

        const int pstep = 2 * nwarps;
        int b = 2 * gwarp;
        float4 iv0, vv0, iv1, vv1;
        if (b < B && act) {
            const float* r0 = stokes + (size_t)b * (4 * NWL);
            iv0 = ((const float4*)r0)[lane];
            vv0 = ((const float4*)(r0 + 3 * NWL))[lane];
            iv1 = ((const float4*)(r0 + 4 * NWL))[lane];
            vv1 = ((const float4*)(r0 + 7 * NWL))[lane];
        } else {
            iv0 = iv1 = vv0 = vv1 = make_float4(0.f,0.f,0.f,0.f);
        }

        while (b < B) {
            const int bn = b + pstep;
            float4 ivn0, vvn0, ivn1, vvn1;
            if (bn < B && act) {                  // prefetch next pair
                const float* rn = stokes + (size_t)bn * (4 * NWL);
                ivn0 = ((const float4*)rn)[lane];
                vvn0 = ((const float4*)(rn + 3 * NWL))[lane];
                ivn1 = ((const float4*)(rn + 4 * NWL))[lane];
                vvn1 = ((const float4*)(rn + 7 * NWL))[lane];
            } else {
                ivn0 = ivn1 = vvn0 = vvn1 = make_float4(0.f,0.f,0.f,0.f);
            }

            float ip0 = __shfl_up_sync(FULL, iv0.w, 1);
            float in0 = __shfl_down_sync(FULL, iv0.x, 1);
            float ip1 = __shfl_up_sync(FULL, iv1.w, 1);
            float in1 = __shfl_down_sync(FULL, iv1.x, 1);

            float v0=0.f,v1=0.f,v2=0.f,v3=0.f,v4=0.f,v5=0.f,v6=0.f,v7=0.f;
            if (act) {
                float d0 = ((lane == 0)  ? (iv0.y - iv0.x) : 0.5f * (iv0.y - ip0)) * ig.x;
                float d1 = 0.5f * (iv0.z - iv0.x) * ig.y;
                float d2 = ((lane == 27) ? (iv0.z - iv0.y) : 0.5f * (iv0.w - iv0.y)) * ig.z;
                float d3 = 0.5f * (in0 - iv0.z) * ig.w;
                float vw0 = (lane == 27) ? 0.0f : vv0.w;
                v0 = d0 + d1 + d2 + d3;
                v1 = vv0.x + vv0.y + vv0.z + vw0;
                v2 = d0*d0 + d1*d1 + d2*d2 + d3*d3;
                v3 = d0*vv0.x + d1*vv0.y + d2*vv0.z + d3*vw0;
                float e0 = ((lane == 0)  ? (iv1.y - iv1.x) : 0.5f * (iv1.y - ip1)) * ig.x;
                float e1 = 0.5f * (iv1.z - iv1.x) * ig.y;
                float e2 = ((lane == 27) ? (iv1.z - iv1.y) : 0.5f * (iv1.w - iv1.y)) * ig.z;
                float e3 = 0.5f * (in1 - iv1.z) * ig.w;
                float vw1 = (lane == 27) ? 0.0f : vv1.w;
                v4 = e0 + e1 + e2 + e3;
                v5 = vv1.x + vv1.y + vv1.z + vw1;
                v6 = e0*e0 + e1*e1 + e2*e2 + e3*e3;
                v7 = e0*vv1.x + e1*vv1.y + e2*vv1.z + e3*vw1;
            }

            // joint 8-value packed butterfly: 16 SHFL
            v0 += __shfl_xor_sync(FULL, v0, 1);
            v1 += __shfl_xor_sync(FULL, v1, 1);
            v2 += __shfl_xor_sync(FULL, v2, 1);
            v3 += __shfl_xor_sync(FULL, v3, 1);
            v4 += __shfl_xor_sync(FULL, v4, 1);
            v5 += __shfl_xor_sync(FULL, v5, 1);
            v6 += __shfl_xor_sync(FULL, v6, 1);
            v7 += __shfl_xor_sync(FULL, v7, 1);
            float p0 = (lane & 1) ? v1 : v0;
            float p1 = (lane & 1) ? v3 : v2;
            float p2 = (lane & 1) ? v5 : v4;
            float p3 = (lane & 1) ? v7 : v6;
            p0 += __shfl_xor_sync(FULL, p0, 2);
            p1 += __shfl_xor_sync(FULL, p1, 2);
            p2 += __shfl_xor_sync(FULL, p2, 2);
            p3 += __shfl_xor_sync(FULL, p3, 2);
            float q0 = (lane & 2) ? p1 : p0;
            float q1 = (lane & 2) ? p3 : p2;
            q0 += __shfl_xor_sync(FULL, q0, 4);
            q1 += __shfl_xor_sync(FULL, q1, 4);
            float r = (lane & 4) ? q1 : q0;
            r += __shfl_xor_sync(FULL, r, 8);
            r += __shfl_xor_sync(FULL, r, 16);
            // lane l holds total of value index (l&7)

            const int base = lane & 4;
            float sd_t  = __shfl_sync(FULL, r, base + 0);
            float sv_t  = __shfl_sync(FULL, r, base + 1);
            float sdd_t = __shfl_sync(FULL, r, base + 2);
            float sdv_t = __shfl_sync(FULL, r, base + 3);

            if ((lane & 27) == 0) {       // lanes 0 and 4 run epilogues concurrently
                const int myb = b + (lane >> 2);
                const float n = (float)NW;
                float pp   = (n * sdv_t - sd_t * sv_t) / (n * sdd_t - sd_t * sd_t);
                float blos = -pp * inv_cal;
                if (fabsf(blos) < 100.0f) {
                    const float* aptr = pred + (size_t)myb * ATM;
                    float pb = (aptr[3] + aptr[7] + aptr[11]) * (1.0f / 3.0f);
                    local_wfa += (double)fabsf(log10f(fabsf(pb)  + 1e-10f) -
                                               log10f(fabsf(blos) + 1e-10f));
                    local_cnt += 1u;
                }
            }
            iv0 = ivn0; vv0 = vvn0; iv1 = ivn1; vv1 = vvn1; b = bn;
        }
    }

    // ======== base loss: grid-wide dynamic chunk queue (ALL warps) ========
    // Base warps start immediately; WFA warps join as soon as their rows finish.
    {
        const size_t total4  = ((size_t)B * ATM) >> 2;          // divisible by CHUNK4? handle tail
        const unsigned n_chunks = (unsigned)((total4 + CHUNK4 - 1) / CHUNK4);
        const float4* p4 = (const float4*)pred;
        const float4* t4 = (const float4*)targ;
        float a0 = 0.f, a1 = 0.f, a2 = 0.f, a3 = 0.f;
        for (;;) {
            unsigned ch = 0;
            if (lane == 0) ch = atomicAdd(&g_chunk, 1u);
            ch = __shfl_sync(FULL, ch, 0);
            if (ch >= n_chunks) break;
            const size_t s   = (size_t)ch * CHUNK4;
            const size_t end = (s + CHUNK4 <= total4) ? s + CHUNK4 : total4;
            size_t i = s + lane;
            // CHUNK4/32 = 16 lane-iterations -> 4 passes of unroll-4
            for (; i + 96 < end; i += 128) {
                float4 pA = p4[i];      float4 tA = t4[i];
                float4 pB = p4[i + 32]; float4 tB = t4[i + 32];
                float4 pC = p4[i + 64]; float4 tC = t4[i + 64];
                float4 pD = p4[i + 96]; float4 tD = t4[i + 96];
                a0 += fabsf(pA.x - tA.x) + fabsf(pA.y - tA.y) + fabsf(pA.z - tA.z) + fabsf(pA.w - tA.w);
                a1 += fabsf(pB.x - tB.x) + fabsf(pB.y - tB.y) + fabsf(pB.z - tB.z) + fabsf(pB.w - tB.w);
                a2 += fabsf(pC.x - tC.x) + fabsf(pC.y - tC.y) + fabsf(pC.z - tC.z) + fabsf(pC.w - tC.w);
                a3 += fabsf(pD.x - tD.x) + fabsf(pD.y - tD.y) + fabsf(pD.z - tD.z) + fabsf(pD.w - tD.w);
            }
            for (; i < end; i += 32) {
                float4 p = p4[i], t = t4[i];
                a0 += fabsf(p.x - t.x) + fabsf(p.y - t.y) + fabsf(p.z - t.z) + fabsf(p.w - t.w);
            }
        }
        local_base = (a0 + a1) + (a2 + a3);
    }

    // ------------- warp + block reduction -------------
    #pragma unroll
    for (int off = 16; off; off >>= 1) {
        local_base += __shfl_xor_sync(FULL, local_base, off);
        local_wfa  += __shfl_xor_sync(FULL, local_wfa,  off);
        local_cnt  += __shfl_xor_sync(FULL, local_cnt,  off);
    }
    __shared__ double s_wfa[WPB];
    __shared__ float  s_base[WPB];
    __shared__ unsigned int s_cnt[WPB];
    if (lane == 0) { s_wfa[warp] = local_wfa; s_base[warp] = local_base; s_cnt[warp] = local_cnt; }
    __syncthreads();

    __shared__ bool s_last;
    if (tid == 0) {
        double w = 0.0, bs = 0.0; unsigned long long c = 0;
        #pragma unroll
        for (int i = 0; i < WPB; i++) { w += s_wfa[i]; bs += (double)s_base[i]; c += s_cnt[i]; }
        atomicAdd(&g_base_sum, bs);
        if (w != 0.0) atomicAdd(&g_wfa_sum, w);
        if (c)        atomicAdd(&g_cnt, c);
        __threadfence();
        unsigned int prev = atomicAdd(&g_done, 1u);
        s_last = (prev == gridDim.x - 1);
    }
    __syncthreads();

    // ------------- last block finalizes + resets for next replay -------------
    if (s_last && tid == 0) {
        double base = *((volatile double*)&g_base_sum) / ((double)B * (double)ATM);
        unsigned long long cnt = *((volatile unsigned long long*)&g_cnt);
        double wfa_m = *((volatile double*)&g_wfa_sum) / (double)(cnt > 0 ? cnt : 1);
        bool apply = (base < 0.0004) && (cnt > 0);
        out[0] = apply ? (float)(0.5 * base + 0.5 * wfa_m) : (float)base;
        out[1] = (float)base;
        out[2] = apply ? (float)wfa_m : 0.0f;
        g_base_sum = 0.0;
        g_wfa_sum  = 0.0;
        g_cnt      = 0ull;
        g_done     = 0u;
        g_chunk    = 0u;
        __threadfence();
    }
}

extern "C" void kernel_launch(void* const* d_in, const int* in_sizes, int n_in,
                              void* d_out, int out_size) {
    const float* stokes = (const float*)d_in[0];   // (B, 4, 112)
    const float* pred   = (const float*)d_in[1];   // (B, 84)
    const float* targ   = (const float*)d_in[2];   // (B, 84)
    const float* wl     = (const float*)d_in[3];   // (112,)
    const int B = in_sizes[0] / (4 * NWL);
    wfa_fused_kernel<<<BLOCKS, THREADS>>>(stokes, pred, targ, wl, (float*)d_out, B);
}

// round 17
// speedup vs baseline: 2.5701x; 1.1676x over previous
#include <cuda_runtime.h>

#define NWL 112
#define NW  111
#define ATM 84
#define THREADS 256
#define WPB (THREADS / 32)
#define WFA_WARPS 6
#define BASE_WARPS (WPB - WFA_WARPS)
#define BLOCKS 888            // 148 SMs * 6 resident blocks -> single wave

__device__ double g_base_sum;   // zero-init at load; reset by finalizer each run
__device__ double g_wfa_sum;
__device__ unsigned long long g_cnt;
__device__ unsigned int g_done;

__global__ void __launch_bounds__(THREADS, 6)
wfa_fused_kernel(const float* __restrict__ stokes,
                 const float* __restrict__ pred,
                 const float* __restrict__ targ,
                 const float* __restrict__ wl,
                 float* __restrict__ out, int B) {
    const int tid   = threadIdx.x;
    const int lane  = tid & 31;
    const int warp  = tid >> 5;
    const unsigned FULL = 0xffffffffu;

    double local_wfa = 0.0;
    float  local_base = 0.f;
    unsigned int local_cnt = 0;

    if (warp < WFA_WARPS) {
        // ========== WFA warps: warp per row-pair, occupancy-covered ==========
        const int gwarp  = blockIdx.x * WFA_WARPS + warp;
        const int nwarps = BLOCKS * WFA_WARPS;
        const float inv_cal = 1.0f / (4.6686e-13f * (6301.5f * 6301.5f) * 1.5f);
        const bool act = (lane < 28);            // 28 float4 cover [0..111]

        // per-lane inverse wavelength gradient (row-invariant)
        float4 ig = make_float4(0.f, 0.f, 0.f, 0.f);
        float4 w4 = act ? ((const float4*)wl)[lane] : make_float4(0.f, 0.f, 0.f, 0.f);
        float wprev = __shfl_up_sync(FULL, w4.w, 1);
        float wnext = __shfl_down_sync(FULL, w4.x, 1);
        if (act) {
            float g0 = (lane == 0)  ? (w4.y - w4.x) : 0.5f * (w4.y - wprev);
            float g1 = 0.5f * (w4.z - w4.x);
            float g2 = (lane == 27) ? (w4.z - w4.y) : 0.5f * (w4.w - w4.y);
            ig.x = 1.0f / g0;
            ig.y = 1.0f / g1;
            ig.z = 1.0f / g2;
            ig.w = (lane == 27) ? 0.0f : 1.0f / (0.5f * (wnext - w4.z));  // j=111 excluded
        }

        const int pstep = 2 * nwarps;
        for (int b = 2 * gwarp; b < B; b += pstep) {
            const float* r0 = stokes + (size_t)b * (4 * NWL);
            float4 iv0, vv0, iv1, vv1;
            if (act) {
                iv0 = ((const float4*)r0)[lane];
                vv0 = ((const float4*)(r0 + 3 * NWL))[lane];
                iv1 = ((const float4*)(r0 + 4 * NWL))[lane];
                vv1 = ((const float4*)(r0 + 7 * NWL))[lane];
            } else {
                iv0 = iv1 = vv0 = vv1 = make_float4(0.f,0.f,0.f,0.f);
            }

            float ip0 = __shfl_up_sync(FULL, iv0.w, 1);
            float in0 = __shfl_down_sync(FULL, iv0.x, 1);
            float ip1 = __shfl_up_sync(FULL, iv1.w, 1);
            float in1 = __shfl_down_sync(FULL, iv1.x, 1);

            float v0=0.f,v1=0.f,v2=0.f,v3=0.f,v4=0.f,v5=0.f,v6=0.f,v7=0.f;
            if (act) {
                float d0 = ((lane == 0)  ? (iv0.y - iv0.x) : 0.5f * (iv0.y - ip0)) * ig.x;
                float d1 = 0.5f * (iv0.z - iv0.x) * ig.y;
                float d2 = ((lane == 27) ? (iv0.z - iv0.y) : 0.5f * (iv0.w - iv0.y)) * ig.z;
                float d3 = 0.5f * (in0 - iv0.z) * ig.w;   // ig.w==0 on lane 27
                float vw0 = (lane == 27) ? 0.0f : vv0.w;
                v0 = d0 + d1 + d2 + d3;
                v1 = vv0.x + vv0.y + vv0.z + vw0;
                v2 = d0*d0 + d1*d1 + d2*d2 + d3*d3;
                v3 = d0*vv0.x + d1*vv0.y + d2*vv0.z + d3*vw0;
                float e0 = ((lane == 0)  ? (iv1.y - iv1.x) : 0.5f * (iv1.y - ip1)) * ig.x;
                float e1 = 0.5f * (iv1.z - iv1.x) * ig.y;
                float e2 = ((lane == 27) ? (iv1.z - iv1.y) : 0.5f * (iv1.w - iv1.y)) * ig.z;
                float e3 = 0.5f * (in1 - iv1.z) * ig.w;
                float vw1 = (lane == 27) ? 0.0f : vv1.w;
                v4 = e0 + e1 + e2 + e3;
                v5 = vv1.x + vv1.y + vv1.z + vw1;
                v6 = e0*e0 + e1*e1 + e2*e2 + e3*e3;
                v7 = e0*vv1.x + e1*vv1.y + e2*vv1.z + e3*vw1;
            }

            // joint 8-value packed butterfly: 16 SHFL
            v0 += __shfl_xor_sync(FULL, v0, 1);
            v1 += __shfl_xor_sync(FULL, v1, 1);
            v2 += __shfl_xor_sync(FULL, v2, 1);
            v3 += __shfl_xor_sync(FULL, v3, 1);
            v4 += __shfl_xor_sync(FULL, v4, 1);
            v5 += __shfl_xor_sync(FULL, v5, 1);
            v6 += __shfl_xor_sync(FULL, v6, 1);
            v7 += __shfl_xor_sync(FULL, v7, 1);
            float p0 = (lane & 1) ? v1 : v0;
            float p1 = (lane & 1) ? v3 : v2;
            float p2 = (lane & 1) ? v5 : v4;
            float p3 = (lane & 1) ? v7 : v6;
            p0 += __shfl_xor_sync(FULL, p0, 2);
            p1 += __shfl_xor_sync(FULL, p1, 2);
            p2 += __shfl_xor_sync(FULL, p2, 2);
            p3 += __shfl_xor_sync(FULL, p3, 2);
            float q0 = (lane & 2) ? p1 : p0;
            float q1 = (lane & 2) ? p3 : p2;
            q0 += __shfl_xor_sync(FULL, q0, 4);
            q1 += __shfl_xor_sync(FULL, q1, 4);
            float r = (lane & 4) ? q1 : q0;
            r += __shfl_xor_sync(FULL, r, 8);
            r += __shfl_xor_sync(FULL, r, 16);
            // lane l holds total of value index (l&7)

            // gather: epilogue lanes (0,4) satisfy lane==base, so sd_t = r locally
            const int base = lane & 4;
            float sv_t  = __shfl_sync(FULL, r, base + 1);
            float sdd_t = __shfl_sync(FULL, r, base + 2);
            float sdv_t = __shfl_sync(FULL, r, base + 3);

            if ((lane & 27) == 0) {       // lanes 0 and 4 run epilogues concurrently
                const float sd_t = r;      // own value: index base+0
                const int myb = b + (lane >> 2);
                const float n = (float)NW;
                float pp   = (n * sdv_t - sd_t * sv_t) / (n * sdd_t - sd_t * sd_t);
                float blos = -pp * inv_cal;
                if (fabsf(blos) < 100.0f) {
                    const float* aptr = pred + (size_t)myb * ATM;
                    float pb = (aptr[3] + aptr[7] + aptr[11]) * (1.0f / 3.0f);
                    local_wfa += (double)fabsf(log10f(fabsf(pb)  + 1e-10f) -
                                               log10f(fabsf(blos) + 1e-10f));
                    local_cnt += 1u;
                }
            }
        }
    } else {
        // ================= base warps: mean |pred - targ| =================
        const int bwarp   = blockIdx.x * BASE_WARPS + (warp - WFA_WARPS);
        const size_t total4 = ((size_t)B * ATM) >> 2;
        const float4* p4 = (const float4*)pred;
        const float4* t4 = (const float4*)targ;
        const size_t stride = (size_t)BLOCKS * BASE_WARPS * 32;
        size_t i = (size_t)bwarp * 32 + lane;

        float a0 = 0.f, a1 = 0.f, a2 = 0.f, a3 = 0.f;
        // 4-deep unroll: 8 independent float4 loads in flight
        for (; i + 3 * stride < total4; i += 4 * stride) {
            float4 pA = p4[i];              float4 tA = t4[i];
            float4 pB = p4[i + stride];     float4 tB = t4[i + stride];
            float4 pC = p4[i + 2 * stride]; float4 tC = t4[i + 2 * stride];
            float4 pD = p4[i + 3 * stride]; float4 tD = t4[i + 3 * stride];
            a0 += fabsf(pA.x - tA.x) + fabsf(pA.y - tA.y) + fabsf(pA.z - tA.z) + fabsf(pA.w - tA.w);
            a1 += fabsf(pB.x - tB.x) + fabsf(pB.y - tB.y) + fabsf(pB.z - tB.z) + fabsf(pB.w - tB.w);
            a2 += fabsf(pC.x - tC.x) + fabsf(pC.y - tC.y) + fabsf(pC.z - tC.z) + fabsf(pC.w - tC.w);
            a3 += fabsf(pD.x - tD.x) + fabsf(pD.y - tD.y) + fabsf(pD.z - tD.z) + fabsf(pD.w - tD.w);
        }
        for (; i < total4; i += stride) {
            float4 p = p4[i], t = t4[i];
            a0 += fabsf(p.x - t.x) + fabsf(p.y - t.y) + fabsf(p.z - t.z) + fabsf(p.w - t.w);
        }
        local_base = (a0 + a1) + (a2 + a3);
    }

    // ------------- warp + block reduction -------------
    #pragma unroll
    for (int off = 16; off; off >>= 1) {
        local_base += __shfl_xor_sync(FULL, local_base, off);
        local_wfa  += __shfl_xor_sync(FULL, local_wfa,  off);
        local_cnt  += __shfl_xor_sync(FULL, local_cnt,  off);
    }
    __shared__ double s_wfa[WPB];
    __shared__ float  s_base[WPB];
    __shared__ unsigned int s_cnt[WPB];
    if (lane == 0) { s_wfa[warp] = local_wfa; s_base[warp] = local_base; s_cnt[warp] = local_cnt; }
    __syncthreads();

    __shared__ bool s_last;
    if (tid == 0) {
        double w = 0.0, bs = 0.0; unsigned long long c = 0;
        #pragma unroll
        for (int i = 0; i < WPB; i++) { w += s_wfa[i]; bs += (double)s_base[i]; c += s_cnt[i]; }
        atomicAdd(&g_base_sum, bs);
        if (w != 0.0) atomicAdd(&g_wfa_sum, w);
        if (c)        atomicAdd(&g_cnt, c);
        __threadfence();
        unsigned int prev = atomicAdd(&g_done, 1u);
        s_last = (prev == gridDim.x - 1);
    }
    __syncthreads();

    // ------------- last block finalizes + resets for next replay -------------
    if (s_last && tid == 0) {
        double base = *((volatile double*)&g_base_sum) / ((double)B * (double)ATM);
        unsigned long long cnt = *((volatile unsigned long long*)&g_cnt);
        double wfa_m = *((volatile double*)&g_wfa_sum) / (double)(cnt > 0 ? cnt : 1);
        bool apply = (base < 0.0004) && (cnt > 0);
        out[0] = apply ? (float)(0.5 * base + 0.5 * wfa_m) : (float)base;
        out[1] = (float)base;
        out[2] = apply ? (float)wfa_m : 0.0f;
        g_base_sum = 0.0;
        g_wfa_sum  = 0.0;
        g_cnt      = 0ull;
        g_done     = 0u;
        __threadfence();
    }
}

extern "C" void kernel_launch(void* const* d_in, const int* in_sizes, int n_in,
                              void* d_out, int out_size) {
    const float* stokes = (const float*)d_in[0];   // (B, 4, 112)
    const float* pred   = (const float*)d_in[1];   // (B, 84)
    const float* targ   = (const float*)d_in[2];   // (B, 84)
    const float* wl     = (const float*)d_in[3];   // (112,)
    const int B = in_sizes[0] / (4 * NWL);
    wfa_fused_kernel<<<BLOCKS, THREADS>>>(stokes, pred, targ, wl, (float*)d_out, B);
}